// round 17
// baseline (speedup 1.0000x reference)
#include <cuda_runtime.h>
#include <cuda_fp16.h>
#include <stdint.h>

#define NUM_USERS 100000
#define NUM_ITEMS 50000
#define N_NODES   (NUM_USERS + NUM_ITEMS)   // 150000
#define EMBED_DIM 64
#define N_EDGES   1000000

#define CSR_MAX   (N_EDGES + 3 * N_NODES)   // padded-to-4 bound (1.45M edges)

#define SCAN_BS   1024
#define N_SCAN_BLOCKS ((N_NODES + SCAN_BS - 1) / SCAN_BS)   // 147

#define A_FLAG (1u << 30)
#define P_FLAG (1u << 31)
#define VAL_MASK 0x3FFFFFFFu

// ---- static device scratch (no allocation allowed) ----
__device__ int      g_deg[N_NODES];
__device__ float    g_dinv[N_NODES];
__device__ int      g_off[N_NODES + 1];    // padded exclusive prefix (immutable)
__device__ int      g_cur[N_NODES];        // scatter cursors (zeroed in k_scan)
__device__ unsigned g_part[N_SCAN_BLOCKS]; // lookback state (zeroed in k_degree)
__device__ int2     g_csr[CSR_MAX];        // {src, norm_bits}; pads = {0,0} via memset
// fp16 embeddings: row = 64 halves = 16 lanes x uint2 (8B) = 128 bytes
__device__ uint2    g_h0[N_NODES * 16];
__device__ uint2    g_h1[N_NODES * 16];
__device__ uint2    g_h2[N_NODES * 16];

// -------------------- setup kernels --------------------

// 2 edges per thread (int2 loads); also zeroes lookback state for k_scan.
__global__ void k_degree(const int* __restrict__ edge_index) {
    int t = blockIdx.x * blockDim.x + threadIdx.x;
    if (t < N_SCAN_BLOCKS) g_part[t] = 0;
    if (t < N_EDGES / 2) {
        int2 d2 = ((const int2*)(edge_index + N_EDGES))[t];
        atomicAdd(&g_deg[d2.x], 1);
        atomicAdd(&g_deg[d2.y], 1);
    }
}

// decoupled-lookback exclusive scan of PADDED degrees; emits dinv, zeroes
// scatter cursors, converts emb->fp16 for this block's range in the tail.
__global__ void __launch_bounds__(SCAN_BS) k_scan(const float4* __restrict__ emb) {
    __shared__ int s_wt[32];
    __shared__ int s_run;

    int tid  = threadIdx.x;
    int bid  = blockIdx.x;
    int lane = tid & 31;
    int wid  = tid >> 5;
    int i    = bid * SCAN_BS + tid;

    int d = (i < N_NODES) ? g_deg[i] : 0;
    if (i < N_NODES) {
        g_dinv[i] = (d > 0) ? rsqrtf((float)d) : 0.0f;
        g_cur[i]  = 0;
    }
    int v = (d + 3) & ~3;                        // padded degree

    int inc = v;
    #pragma unroll
    for (int s = 1; s < 32; s <<= 1) {
        int t = __shfl_up_sync(0xffffffffu, inc, s);
        if (lane >= s) inc += t;
    }
    if (lane == 31) s_wt[wid] = inc;
    __syncthreads();

    if (wid == 0) {
        int wv = s_wt[lane];
        int winc = wv;
        #pragma unroll
        for (int s = 1; s < 32; s <<= 1) {
            int t = __shfl_up_sync(0xffffffffu, winc, s);
            if (lane >= s) winc += t;
        }
        s_wt[lane] = winc;
        if (lane == 31)
            atomicExch(&g_part[bid], A_FLAG | (unsigned)winc);

        int running = 0;
        int look = bid - 1;
        while (look >= 0) {
            int idx = look - lane;
            unsigned w;
            if (idx >= 0) {
                volatile unsigned* p = (volatile unsigned*)&g_part[idx];
                do { w = *p; } while ((w & (A_FLAG | P_FLAG)) == 0);
            } else {
                w = P_FLAG;
            }
            unsigned pm = __ballot_sync(0xffffffffu, (w & P_FLAG) != 0);
            int firstP = pm ? (__ffs(pm) - 1) : 32;
            int contrib = (lane <= firstP) ? (int)(w & VAL_MASK) : 0;
            #pragma unroll
            for (int s = 16; s; s >>= 1) contrib += __shfl_down_sync(0xffffffffu, contrib, s);
            contrib = __shfl_sync(0xffffffffu, contrib, 0);
            running += contrib;
            if (firstP < 32) break;
            look -= 32;
        }
        if (lane == 31)
            atomicExch(&g_part[bid], P_FLAG | (unsigned)(running + winc));
        if (lane == 0) s_run = running;
    }
    __syncthreads();

    int excl = (wid ? s_wt[wid - 1] : 0) + (inc - v) + s_run;
    if (i < N_NODES) g_off[i] = excl;
    if (i == N_NODES - 1) g_off[N_NODES] = excl + v;

    // tail: h0 = fp16(emb) for this block's node range (1:1 float4 -> uint2)
    int base16 = bid * SCAN_BS * 16;
    #pragma unroll
    for (int k = 0; k < 16; k++) {
        int j = base16 + k * SCAN_BS + tid;
        if (j < N_NODES * 16) {
            float4 e = emb[j];
            uint2 o;
            *(__half2*)&o.x = __float22half2_rn(make_float2(e.x, e.y));
            *(__half2*)&o.y = __float22half2_rn(make_float2(e.z, e.w));
            g_h0[j] = o;
        }
    }
}

// scatter 2 edges per thread; g_off immutable, cursors in g_cur.
__global__ void k_scatter(const int* __restrict__ edge_index) {
    int t = blockIdx.x * blockDim.x + threadIdx.x;
    if (t < N_EDGES / 2) {
        int2 s2 = ((const int2*)edge_index)[t];
        int2 d2 = ((const int2*)(edge_index + N_EDGES))[t];
        int p0 = g_off[d2.x] + atomicAdd(&g_cur[d2.x], 1);
        g_csr[p0] = make_int2(s2.x, __float_as_int(g_dinv[s2.x] * g_dinv[d2.x]));
        int p1 = g_off[d2.y] + atomicAdd(&g_cur[d2.y], 1);
        g_csr[p1] = make_int2(s2.y, __float_as_int(g_dinv[s2.y] * g_dinv[d2.y]));
    }
}

// -------------------- propagation --------------------
// 2 nodes per warp: 16 lanes per node, uint2 (4 halves) per lane = 128B row.
// Padded CSR (x4): straight-line trips, zero clamping ALU. Per trip:
// 2x int4 csr LDG.128 (4 edges) + 4 gather LDG.64 + cvt/FMA. Pads are
// {src=0, w=0}: row 0 is L1-hot, weight-0 FMAs are no-ops.
__device__ __forceinline__ float4 gather_h(const uint2* __restrict__ hx,
                                           int beg, int nt, int qlane) {
    float4 sum = make_float4(0.0f, 0.0f, 0.0f, 0.0f);
    const int4* cp = (const int4*)(g_csr + beg);   // beg multiple of 4 -> 16B aligned
    for (int t = 0; t < nt; t++) {
        int4 a = cp[2 * t];                        // {src0, w0, src1, w1}
        int4 b = cp[2 * t + 1];                    // {src2, w2, src3, w3}
        uint2 v0 = hx[(size_t)a.x * 16 + qlane];
        uint2 v1 = hx[(size_t)a.z * 16 + qlane];
        uint2 v2 = hx[(size_t)b.x * 16 + qlane];
        uint2 v3 = hx[(size_t)b.z * 16 + qlane];
        float w0 = __int_as_float(a.y);
        float w1 = __int_as_float(a.w);
        float w2 = __int_as_float(b.y);
        float w3 = __int_as_float(b.w);
        float2 f;
        f = __half22float2(*(__half2*)&v0.x); sum.x = fmaf(f.x, w0, sum.x); sum.y = fmaf(f.y, w0, sum.y);
        f = __half22float2(*(__half2*)&v0.y); sum.z = fmaf(f.x, w0, sum.z); sum.w = fmaf(f.y, w0, sum.w);
        f = __half22float2(*(__half2*)&v1.x); sum.x = fmaf(f.x, w1, sum.x); sum.y = fmaf(f.y, w1, sum.y);
        f = __half22float2(*(__half2*)&v1.y); sum.z = fmaf(f.x, w1, sum.z); sum.w = fmaf(f.y, w1, sum.w);
        f = __half22float2(*(__half2*)&v2.x); sum.x = fmaf(f.x, w2, sum.x); sum.y = fmaf(f.y, w2, sum.y);
        f = __half22float2(*(__half2*)&v2.y); sum.z = fmaf(f.x, w2, sum.z); sum.w = fmaf(f.y, w2, sum.w);
        f = __half22float2(*(__half2*)&v3.x); sum.x = fmaf(f.x, w3, sum.x); sum.y = fmaf(f.y, w3, sum.y);
        f = __half22float2(*(__half2*)&v3.y); sum.z = fmaf(f.x, w3, sum.z); sum.w = fmaf(f.y, w3, sum.w);
    }
    return sum;
}

__device__ __forceinline__ uint2 pack_h(float4 s) {
    uint2 o;
    *(__half2*)&o.x = __float22half2_rn(make_float2(s.x, s.y));
    *(__half2*)&o.y = __float22half2_rn(make_float2(s.z, s.w));
    return o;
}

__global__ void __launch_bounds__(256) k_prop1() {
    int gtid = blockIdx.x * blockDim.x + threadIdx.x;
    int node = gtid >> 4, qlane = gtid & 15;
    if (node >= N_NODES) return;
    int beg = g_off[node];
    int nt  = (g_off[node + 1] - beg) >> 2;
    float4 sum = gather_h(g_h0, beg, nt, qlane);
    g_h1[(size_t)node * 16 + qlane] = pack_h(sum);
}

__global__ void __launch_bounds__(256) k_prop2() {
    int gtid = blockIdx.x * blockDim.x + threadIdx.x;
    int node = gtid >> 4, qlane = gtid & 15;
    if (node >= N_NODES) return;
    int beg = g_off[node];
    int nt  = (g_off[node + 1] - beg) >> 2;
    float4 sum = gather_h(g_h1, beg, nt, qlane);
    g_h2[(size_t)node * 16 + qlane] = pack_h(sum);
}

// layer 3 + epilogue: out = 0.25*(emb_fp32 + h1 + h2 + A~*h2)
__global__ void __launch_bounds__(256) k_prop_last(const float4* __restrict__ emb,
                                                   float4* __restrict__ out) {
    int gtid = blockIdx.x * blockDim.x + threadIdx.x;
    int node = gtid >> 4, qlane = gtid & 15;
    if (node >= N_NODES) return;
    int beg = g_off[node];
    int nt  = (g_off[node + 1] - beg) >> 2;
    float4 sum = gather_h(g_h2, beg, nt, qlane);

    size_t oi = (size_t)node * 16 + qlane;
    float4 e0 = emb[oi];
    uint2 u1 = g_h1[oi];
    uint2 u2 = g_h2[oi];
    float2 a1lo = __half22float2(*(__half2*)&u1.x);
    float2 a1hi = __half22float2(*(__half2*)&u1.y);
    float2 a2lo = __half22float2(*(__half2*)&u2.x);
    float2 a2hi = __half22float2(*(__half2*)&u2.y);
    float4 o;
    o.x = 0.25f * (e0.x + a1lo.x + a2lo.x + sum.x);
    o.y = 0.25f * (e0.y + a1lo.y + a2lo.y + sum.y);
    o.z = 0.25f * (e0.z + a1hi.x + a2hi.x + sum.z);
    o.w = 0.25f * (e0.w + a1hi.y + a2hi.y + sum.w);
    out[oi] = o;
}

// -------------------- launch --------------------

extern "C" void kernel_launch(void* const* d_in, const int* in_sizes, int n_in,
                              void* d_out, int out_size) {
    const int*   edge_index = (const int*)d_in[0];     // int32
    const float* emb_weight = (const float*)d_in[1];
    float*       out        = (float*)d_out;

    void *deg_ptr, *csr_ptr;
    cudaGetSymbolAddress(&deg_ptr, g_deg);
    cudaGetSymbolAddress(&csr_ptr, g_csr);
    cudaMemsetAsync(deg_ptr, 0, N_NODES * sizeof(int), 0);
    cudaMemsetAsync(csr_ptr, 0, CSR_MAX * sizeof(int2), 0);

    const int BS = 256;
    int geh = (N_EDGES / 2 + BS - 1) / BS;

    k_degree<<<geh, BS>>>(edge_index);                              // kernel 1
    k_scan<<<N_SCAN_BLOCKS, SCAN_BS>>>((const float4*)emb_weight);  // kernel 2 (+h0,+cur)
    k_scatter<<<geh, BS>>>(edge_index);                             // kernel 3

    int gp = (N_NODES * 16 + BS - 1) / BS;                          // 16 threads/node
    k_prop1<<<gp, BS>>>();                                          // kernel 4 <- ncu
    k_prop2<<<gp, BS>>>();                                          // kernel 5
    k_prop_last<<<gp, BS>>>((const float4*)emb_weight, (float4*)out); // kernel 6
}